// round 14
// baseline (speedup 1.0000x reference)
#include <cuda_runtime.h>
#include <cstdint>
#include <cstddef>

#define S_LEN 8192
#define HID   1024
#define G4    4096   // 4*HID

// ---------------- scratch (device globals: allocation-free) ----------------
// gates layout: [S][HID][4]  (4 gate values for hidden j contiguous)
__device__ float g_gates[(size_t)S_LEN * G4];   // 128 MB
__device__ float g_yA[(size_t)S_LEN * HID];     // 32 MB: layer outputs ping
__device__ float g_yB[(size_t)S_LEN * HID];     // 32 MB: layer outputs pong
// hidden state values, double-buffered by step parity (bare values; ordering
// carried entirely by the per-block epoch flags below)
__device__ __align__(16) float g_hv[2][HID];
// per-producer-block epoch flags: flag[b] = t+1 once block b has published
// its 8 h values for step t. Release/acquire (CG grid-sync pattern, same
// family as the validated R12 counters) but with NO atomic accumulation and
// per-block granularity: consumer staging thread tid depends on exactly one
// producer block (tid/2), so it waits only for ITS producer.
__device__ unsigned g_flag[128];

// ---------------- packed f32x2 helpers (sm_103a FFMA2) ----------------
__device__ __forceinline__ void ffma2(unsigned long long& d,
                                      unsigned long long a,
                                      unsigned long long b) {
    asm("fma.rn.f32x2 %0, %1, %2, %0;" : "+l"(d) : "l"(a), "l"(b));
}
__device__ __forceinline__ unsigned long long pack2(float x, float y) {
    unsigned long long r;
    asm("mov.b64 %0, {%1, %2};" : "=l"(r)
        : "r"(__float_as_uint(x)), "r"(__float_as_uint(y)));
    return r;
}
__device__ __forceinline__ float2 unpack2(unsigned long long v) {
    unsigned int lo, hi;
    asm("mov.b64 {%0, %1}, %2;" : "=r"(lo), "=r"(hi) : "l"(v));
    float2 r; r.x = __uint_as_float(lo); r.y = __uint_as_float(hi);
    return r;
}

__device__ __forceinline__ float sigmoidf_(float x) {
    return __fdividef(1.0f, 1.0f + __expf(-x));
}
// fast, overflow-safe tanh: tanh(x) = sign(x) * (1-e)/(1+e), e = exp(-2|x|)
__device__ __forceinline__ float tanhf_(float x) {
    float e = __expf(-2.0f * fabsf(x));
    float r = __fdividef(1.0f - e, 1.0f + e);
    return copysignf(r, x);
}

// release/acquire epoch ops (the cooperative-groups grid-sync pattern)
__device__ __forceinline__ unsigned ldacq(const unsigned* p) {
    unsigned v;
    asm volatile("ld.acquire.gpu.global.u32 %0, [%1];" : "=r"(v) : "l"(p));
    return v;
}
__device__ __forceinline__ void strel(unsigned* p, unsigned v) {
    asm volatile("st.release.gpu.global.u32 [%0], %1;" :: "l"(p), "r"(v) : "memory");
}

// ---------------- zero the epoch flags (before every scan) -----------------
__global__ void zero_flag_kernel() {
    if (threadIdx.x < 128) g_flag[threadIdx.x] = 0u;
}

// ---------------- GEMM: gates[S][HID][4] = X[S,K] @ W[4H,K]^T + b ----------
// BM=BN=128, BK=16, 256 threads, 8x8 microtile, f32x2 packed FMAs.
__global__ __launch_bounds__(256)
void gemm_xwt(const float* __restrict__ Xext, int xsel,
              const float* __restrict__ W, const float* __restrict__ bias,
              int K)
{
    const float* X = (xsel == 0) ? Xext : (xsel == 1 ? g_yA : g_yB);

    __shared__ float a_s[16][128];
    __shared__ float b_s[16][128];

    const int tid = threadIdx.x;
    const int bm = blockIdx.y * 128;
    const int bn = blockIdx.x * 128;
    const int tx = tid & 15;   // 0..15 -> N
    const int ty = tid >> 4;   // 0..15 -> M

    unsigned long long acc[8][4];
#pragma unroll
    for (int i = 0; i < 8; ++i)
#pragma unroll
        for (int jp = 0; jp < 4; ++jp) acc[i][jp] = 0ull;

    for (int k0 = 0; k0 < K; k0 += 16) {
#pragma unroll
        for (int r = 0; r < 2; ++r) {
            int q   = tid + r * 256;      // 0..511 float4 slots
            int row = q >> 2;             // 0..127
            int kq  = (q & 3) << 2;       // 0,4,8,12
            float4 va = *(const float4*)(X + (size_t)(bm + row) * K + k0 + kq);
            a_s[kq + 0][row] = va.x; a_s[kq + 1][row] = va.y;
            a_s[kq + 2][row] = va.z; a_s[kq + 3][row] = va.w;
            float4 vb = *(const float4*)(W + (size_t)(bn + row) * K + k0 + kq);
            b_s[kq + 0][row] = vb.x; b_s[kq + 1][row] = vb.y;
            b_s[kq + 2][row] = vb.z; b_s[kq + 3][row] = vb.w;
        }
        __syncthreads();
#pragma unroll
        for (int kk = 0; kk < 16; ++kk) {
            float4 a0 = *(const float4*)&a_s[kk][ty * 8];
            float4 a1 = *(const float4*)&a_s[kk][ty * 8 + 4];
            float4 b0 = *(const float4*)&b_s[kk][tx * 8];
            float4 b1 = *(const float4*)&b_s[kk][tx * 8 + 4];
            unsigned long long bp0 = pack2(b0.x, b0.y);
            unsigned long long bp1 = pack2(b0.z, b0.w);
            unsigned long long bp2 = pack2(b1.x, b1.y);
            unsigned long long bp3 = pack2(b1.z, b1.w);
            float av[8] = {a0.x, a0.y, a0.z, a0.w, a1.x, a1.y, a1.z, a1.w};
#pragma unroll
            for (int i = 0; i < 8; ++i) {
                unsigned long long ap = pack2(av[i], av[i]);
                ffma2(acc[i][0], ap, bp0);
                ffma2(acc[i][1], ap, bp1);
                ffma2(acc[i][2], ap, bp2);
                ffma2(acc[i][3], ap, bp3);
            }
        }
        __syncthreads();
    }

    // epilogue: scatter into [S][HID][4] interleaved-gate layout
    const int gate = bn >> 10;          // constant per block (bn multiple of 128)
#pragma unroll
    for (int i = 0; i < 8; ++i) {
        size_t row = (size_t)(bm + ty * 8 + i);
#pragma unroll
        for (int jp = 0; jp < 4; ++jp) {
            int col = bn + tx * 8 + jp * 2;
            int jj  = col - (gate << 10);
            float2 v = unpack2(acc[i][jp]);
            g_gates[row * G4 + (size_t)jj * 4 + gate]       = v.x + bias[col];
            g_gates[row * G4 + (size_t)(jj + 1) * 4 + gate] = v.y + bias[col + 1];
        }
    }
}

// ---------------- persistent recurrent scan (one launch per layer) ---------
// 128 blocks x 8 warps; warp w of block b owns hidden index j = b*8+w and
// computes all 4 gate rows for j. w_hh in registers (128 fp32/lane).
//
// Inter-SM sync = per-producer-block epoch flags (release/acquire):
//   producer: lane0s st.cg 8 h values -> bar.sync -> tid0 st.release
//             flag[b] = t+1   (no atomics, no accumulation)
//   consumer: staging thread tid polls flag[tid/2] (ld.acquire, 4B,
//             warp-coalesced; traffic ~128KB/round chip-wide) until >= t+1,
//             then ld.cg its 4 bare h values. Early producers' h loads
//             overlap the straggler's wait; one bar gates the GEMV.
// spin(16) then the validated nanosleep(40) fallback.
__global__ __launch_bounds__(256, 1)
void lstm_scan(const float* __restrict__ w_hh, int ysel)
{
    float* y_out = (ysel == 1) ? g_yA : g_yB;

    __shared__ __align__(16) float sm_h[2][HID];   // double-buffered staged h

    const int tid  = threadIdx.x;
    const int lane = tid & 31;
    const int warp = tid >> 5;
    const int j    = blockIdx.x * 8 + warp;    // 0..1023

    // this warp's w_hh slice in registers: w[gate][it] covers
    // k = it*128 + lane*4 .. +3, packed as two f32x2.
    unsigned long long w[4][8][2];
#pragma unroll
    for (int g = 0; g < 4; ++g)
#pragma unroll
        for (int it = 0; it < 8; ++it) {
            union { float4 f4; unsigned long long u[2]; } t;
            t.f4 = *(const float4*)(w_hh + (size_t)(g * HID + j) * HID
                                    + it * 128 + lane * 4);
            w[g][it][0] = t.u[0];
            w[g][it][1] = t.u[1];
        }

    float c = 0.0f;  // cell state (redundant in all lanes)

    // gates prefetch pipeline, 2 steps deep. Warp-uniform float4 load:
    // every lane gets all 4 gate values for its j (same 16B sector).
    const float4* gbase = (const float4*)g_gates + j;   // stride G4/4 per step
    float4 gq  = __ldcg(gbase + (size_t)0 * HID);
    float4 gq1 = __ldcg(gbase + (size_t)1 * HID);

    // this staging thread's producer block and flag
    const unsigned* myflag = &g_flag[tid >> 1];

    for (int t = 0; t < S_LEN; ++t) {
        // prefetch gates for t+2
        float4 gq2 = make_float4(0.f, 0.f, 0.f, 0.f);
        if (t + 2 < S_LEN) gq2 = __ldcg(gbase + (size_t)(t + 2) * HID);

        const int par = (t - 1) & 1;

        if (t > 0) {
            // ---- wait for MY producer block's epoch (flag >= t) ----------
            const unsigned tb = (unsigned)t;   // flag value for step t-1
            unsigned v = ldacq(myflag);
            int spins = 0;
            while (v < tb) {
                if (spins >= 16) __nanosleep(40);   // validated fallback
                ++spins;
                v = ldacq(myflag);                  // RT-paced dependent reload
            }
            // ---- stage h(t-1): thread tid covers h[4*tid .. 4*tid+3] -----
            float4 hv = __ldcg((const float4*)&g_hv[par][4 * tid]);
            *(float4*)&sm_h[par][4 * tid] = hv;
        }
        __syncthreads();

        unsigned long long a0 = 0, a1 = 0, a2 = 0, a3 = 0;
        if (t > 0) {
            // ---- full GEMV (k = 0..1023) from SMEM ----
            const float* hs = sm_h[par];
#pragma unroll
            for (int it = 0; it < 8; ++it) {
                union { float4 f4; unsigned long long u[2]; } hv;
                hv.f4 = *(const float4*)(hs + it * 128 + lane * 4);
                ffma2(a0, hv.u[0], w[0][it][0]); ffma2(a0, hv.u[1], w[0][it][1]);
                ffma2(a1, hv.u[0], w[1][it][0]); ffma2(a1, hv.u[1], w[1][it][1]);
                ffma2(a2, hv.u[0], w[2][it][0]); ffma2(a2, hv.u[1], w[2][it][1]);
                ffma2(a3, hv.u[0], w[3][it][0]); ffma2(a3, hv.u[1], w[3][it][1]);
            }
        }

        float2 p;
        p = unpack2(a0); float si = p.x + p.y;
        p = unpack2(a1); float sf = p.x + p.y;
        p = unpack2(a2); float sg = p.x + p.y;
        p = unpack2(a3); float so = p.x + p.y;
#pragma unroll
        for (int off = 16; off; off >>= 1) {
            si += __shfl_xor_sync(0xffffffffu, si, off);
            sf += __shfl_xor_sync(0xffffffffu, sf, off);
            sg += __shfl_xor_sync(0xffffffffu, sg, off);
            so += __shfl_xor_sync(0xffffffffu, so, off);
        }
        // butterfly left full sums in every lane; all lanes compute the
        // epilogue redundantly (no broadcast shuffles on the chain)
        float i_  = sigmoidf_(si + gq.x);
        float f_  = sigmoidf_(sf + gq.y);
        float gg_ = tanhf_  (sg + gq.z);
        float o_  = sigmoidf_(so + gq.w);
        c = f_ * c + i_ * gg_;
        float hn = o_ * tanhf_(c);
        if (lane == 0) {
            __stcg(&g_hv[t & 1][j], hn);        // bare value publish
            y_out[(size_t)t * HID + j] = hn;
        }
        // ---- release this block's epoch: bar orders all 8 warps' h
        //      publishes before the single release store -------------------
        __syncthreads();
        if (tid == 0) strel(&g_flag[blockIdx.x], (unsigned)(t + 1));

        gq = gq1; gq1 = gq2;
    }
}

// ---------------- final FC: out = h_last . fc_w + fc_b ---------------------
__global__ void fc_kernel(const float* __restrict__ w,
                          const float* __restrict__ b,
                          float* __restrict__ out)
{
    const float* h = g_yB + (size_t)(S_LEN - 1) * HID;
    const int tid = threadIdx.x;
    float s = 0.0f;
    for (int k = tid; k < HID; k += 256) s += h[k] * w[k];
#pragma unroll
    for (int off = 16; off; off >>= 1) s += __shfl_xor_sync(0xffffffffu, s, off);
    __shared__ float red[8];
    if ((tid & 31) == 0) red[tid >> 5] = s;
    __syncthreads();
    if (tid == 0) {
        float tot = 0.0f;
#pragma unroll
        for (int i = 0; i < 8; ++i) tot += red[i];
        out[0] = tot + b[0];
    }
}

// ---------------- launch ----------------------------------------------------
extern "C" void kernel_launch(void* const* d_in, const int* in_sizes, int n_in,
                              void* d_out, int out_size)
{
    (void)in_sizes; (void)n_in; (void)out_size;
    const float* seq   = (const float*)d_in[0];
    const float* w_ih0 = (const float*)d_in[1];
    const float* w_hh0 = (const float*)d_in[2];
    const float* b0    = (const float*)d_in[3];
    const float* w_ih1 = (const float*)d_in[4];
    const float* w_hh1 = (const float*)d_in[5];
    const float* b1    = (const float*)d_in[6];
    const float* w_ih2 = (const float*)d_in[7];
    const float* w_hh2 = (const float*)d_in[8];
    const float* b2    = (const float*)d_in[9];
    const float* w_ih3 = (const float*)d_in[10];
    const float* w_hh3 = (const float*)d_in[11];
    const float* b3    = (const float*)d_in[12];
    const float* fc_w  = (const float*)d_in[13];
    const float* fc_b  = (const float*)d_in[14];
    float* out = (float*)d_out;

    dim3 ggrid(G4 / 128, S_LEN / 128);

    // layer 0
    gemm_xwt<<<ggrid, 256>>>(seq, 0, w_ih0, b0, 256);
    zero_flag_kernel<<<1, 128>>>();
    lstm_scan<<<128, 256>>>(w_hh0, 1);      // -> g_yA
    // layer 1
    gemm_xwt<<<ggrid, 256>>>(nullptr, 1, w_ih1, b1, HID);
    zero_flag_kernel<<<1, 128>>>();
    lstm_scan<<<128, 256>>>(w_hh1, 2);      // -> g_yB
    // layer 2
    gemm_xwt<<<ggrid, 256>>>(nullptr, 2, w_ih2, b2, HID);
    zero_flag_kernel<<<1, 128>>>();
    lstm_scan<<<128, 256>>>(w_hh2, 1);      // -> g_yA
    // layer 3
    gemm_xwt<<<ggrid, 256>>>(nullptr, 1, w_ih3, b3, HID);
    zero_flag_kernel<<<1, 128>>>();
    lstm_scan<<<128, 256>>>(w_hh3, 2);      // -> g_yB
    // head
    fc_kernel<<<1, 256>>>(fc_w, fc_b, out);
}

// round 15
// speedup vs baseline: 2.3726x; 2.3726x over previous
#include <cuda_runtime.h>
#include <cstdint>
#include <cstddef>

#define S_LEN 8192
#define HID   1024
#define G4    4096   // 4*HID

// ---------------- scratch (device globals: allocation-free) ----------------
// gates layout: [S][HID][4]  (4 gate values for hidden j contiguous)
__device__ float g_gates[(size_t)S_LEN * G4];   // 128 MB
__device__ float g_yA[(size_t)S_LEN * HID];     // 32 MB: layer outputs ping
__device__ float g_yB[(size_t)S_LEN * HID];     // 32 MB: layer outputs pong
// hidden state values, double-buffered by step parity (bare values; ordering
// carried entirely by the epoch counters below)
__device__ __align__(16) float g_hv[2][HID];
// epoch counters: [replica 0..7][half 0..1][layer][t].
// Producer block b (after its block barrier) adds 1 to all 8 replicas of
// half = b>=64. Consumer warp w polls replica w of a half until it reaches
// 64. Warp-uniform 4B polls (the R12-validated pattern); replica planes are
// far apart -> no hot line.
__device__ unsigned g_ctr[8][2][4][S_LEN];      // 2 MB

// ---------------- packed f32x2 helpers (sm_103a FFMA2) ----------------
__device__ __forceinline__ void ffma2(unsigned long long& d,
                                      unsigned long long a,
                                      unsigned long long b) {
    asm("fma.rn.f32x2 %0, %1, %2, %0;" : "+l"(d) : "l"(a), "l"(b));
}
__device__ __forceinline__ unsigned long long pack2(float x, float y) {
    unsigned long long r;
    asm("mov.b64 %0, {%1, %2};" : "=l"(r)
        : "r"(__float_as_uint(x)), "r"(__float_as_uint(y)));
    return r;
}
__device__ __forceinline__ float2 unpack2(unsigned long long v) {
    unsigned int lo, hi;
    asm("mov.b64 {%0, %1}, %2;" : "=r"(lo), "=r"(hi) : "l"(v));
    float2 r; r.x = __uint_as_float(lo); r.y = __uint_as_float(hi);
    return r;
}

__device__ __forceinline__ float sigmoidf_(float x) {
    return __fdividef(1.0f, 1.0f + __expf(-x));
}
// fast, overflow-safe tanh: tanh(x) = sign(x) * (1-e)/(1+e), e = exp(-2|x|)
__device__ __forceinline__ float tanhf_(float x) {
    float e = __expf(-2.0f * fabsf(x));
    float r = __fdividef(1.0f - e, 1.0f + e);
    return copysignf(r, x);
}

// release/acquire epoch ops (the cooperative-groups grid-sync pattern)
__device__ __forceinline__ unsigned ldacq(const unsigned* p) {
    unsigned v;
    asm volatile("ld.acquire.gpu.global.u32 %0, [%1];" : "=r"(v) : "l"(p));
    return v;
}
__device__ __forceinline__ void redrel(unsigned* p) {
    asm volatile("red.release.gpu.global.add.u32 [%0], 1;" :: "l"(p) : "memory");
}

// ---------------- zero the epoch counters (fresh every replay) -------------
__global__ void zero_ctr_kernel() {
    int i = blockIdx.x * blockDim.x + threadIdx.x;
    if (i < 8 * 2 * 4 * S_LEN) ((unsigned*)g_ctr)[i] = 0u;
}

// ---------------- GEMM: gates[S][HID][4] = X[S,K] @ W[4H,K]^T + b ----------
// BM=BN=128, BK=16, 256 threads, 8x8 microtile, f32x2 packed FMAs.
__global__ __launch_bounds__(256)
void gemm_xwt(const float* __restrict__ Xext, int xsel,
              const float* __restrict__ W, const float* __restrict__ bias,
              int K)
{
    const float* X = (xsel == 0) ? Xext : (xsel == 1 ? g_yA : g_yB);

    __shared__ float a_s[16][128];
    __shared__ float b_s[16][128];

    const int tid = threadIdx.x;
    const int bm = blockIdx.y * 128;
    const int bn = blockIdx.x * 128;
    const int tx = tid & 15;   // 0..15 -> N
    const int ty = tid >> 4;   // 0..15 -> M

    unsigned long long acc[8][4];
#pragma unroll
    for (int i = 0; i < 8; ++i)
#pragma unroll
        for (int jp = 0; jp < 4; ++jp) acc[i][jp] = 0ull;

    for (int k0 = 0; k0 < K; k0 += 16) {
#pragma unroll
        for (int r = 0; r < 2; ++r) {
            int q   = tid + r * 256;      // 0..511 float4 slots
            int row = q >> 2;             // 0..127
            int kq  = (q & 3) << 2;       // 0,4,8,12
            float4 va = *(const float4*)(X + (size_t)(bm + row) * K + k0 + kq);
            a_s[kq + 0][row] = va.x; a_s[kq + 1][row] = va.y;
            a_s[kq + 2][row] = va.z; a_s[kq + 3][row] = va.w;
            float4 vb = *(const float4*)(W + (size_t)(bn + row) * K + k0 + kq);
            b_s[kq + 0][row] = vb.x; b_s[kq + 1][row] = vb.y;
            b_s[kq + 2][row] = vb.z; b_s[kq + 3][row] = vb.w;
        }
        __syncthreads();
#pragma unroll
        for (int kk = 0; kk < 16; ++kk) {
            float4 a0 = *(const float4*)&a_s[kk][ty * 8];
            float4 a1 = *(const float4*)&a_s[kk][ty * 8 + 4];
            float4 b0 = *(const float4*)&b_s[kk][tx * 8];
            float4 b1 = *(const float4*)&b_s[kk][tx * 8 + 4];
            unsigned long long bp0 = pack2(b0.x, b0.y);
            unsigned long long bp1 = pack2(b0.z, b0.w);
            unsigned long long bp2 = pack2(b1.x, b1.y);
            unsigned long long bp3 = pack2(b1.z, b1.w);
            float av[8] = {a0.x, a0.y, a0.z, a0.w, a1.x, a1.y, a1.z, a1.w};
#pragma unroll
            for (int i = 0; i < 8; ++i) {
                unsigned long long ap = pack2(av[i], av[i]);
                ffma2(acc[i][0], ap, bp0);
                ffma2(acc[i][1], ap, bp1);
                ffma2(acc[i][2], ap, bp2);
                ffma2(acc[i][3], ap, bp3);
            }
        }
        __syncthreads();
    }

    // epilogue: scatter into [S][HID][4] interleaved-gate layout
    const int gate = bn >> 10;          // constant per block (bn multiple of 128)
#pragma unroll
    for (int i = 0; i < 8; ++i) {
        size_t row = (size_t)(bm + ty * 8 + i);
#pragma unroll
        for (int jp = 0; jp < 4; ++jp) {
            int col = bn + tx * 8 + jp * 2;
            int jj  = col - (gate << 10);
            float2 v = unpack2(acc[i][jp]);
            g_gates[row * G4 + (size_t)jj * 4 + gate]       = v.x + bias[col];
            g_gates[row * G4 + (size_t)(jj + 1) * 4 + gate] = v.y + bias[col + 1];
        }
    }
}

// ---------------- persistent recurrent scan (one launch per layer) ---------
// 128 blocks x 8 warps; warp w of block b owns hidden index j = b*8+w and
// computes all 4 gate rows for j. w_hh in registers (128 fp32/lane).
//
// Inter-SM sync = R12's validated release/acquire epoch counters, split into
// two HALF counters so detection/loading of h[512:1024] overlaps GEMV half0:
//   producer: st.cg 8 h values -> bar -> red.release to 8 replicas of
//             half(blockIdx) counter
//   consumer: poll ctrA (warp-uniform 4B) ==64 -> stage h[0:512] -> bar ->
//             GEMV half0 -> poll ctrB ==64 -> stage h[512:] -> bar ->
//             GEMV half1 -> reduce -> epilogue -> publish
// spin(8) then validated nanosleep(40) fallback on every poll.
__global__ __launch_bounds__(256, 1)
void lstm_scan(const float* __restrict__ w_hh, int ysel, int layer)
{
    float* y_out = (ysel == 1) ? g_yA : g_yB;

    __shared__ __align__(16) float sm_h[2][HID];   // double-buffered staged h

    const int tid  = threadIdx.x;
    const int lane = tid & 31;
    const int warp = tid >> 5;
    const int j    = blockIdx.x * 8 + warp;    // 0..1023
    const int half = blockIdx.x >> 6;          // producer half of this block

    // this warp's w_hh slice in registers: w[gate][it] covers
    // k = it*128 + lane*4 .. +3, packed as two f32x2.
    unsigned long long w[4][8][2];
#pragma unroll
    for (int g = 0; g < 4; ++g)
#pragma unroll
        for (int it = 0; it < 8; ++it) {
            union { float4 f4; unsigned long long u[2]; } t;
            t.f4 = *(const float4*)(w_hh + (size_t)(g * HID + j) * HID
                                    + it * 128 + lane * 4);
            w[g][it][0] = t.u[0];
            w[g][it][1] = t.u[1];
        }

    float c = 0.0f;  // cell state (redundant in all lanes)

    // gates prefetch pipeline, 2 steps deep. Warp-uniform float4 load:
    // every lane gets all 4 gate values for its j (same 16B sector).
    const float4* gbase = (const float4*)g_gates + j;   // stride G4/4 per step
    float4 gq  = __ldcg(gbase + (size_t)0 * HID);
    float4 gq1 = __ldcg(gbase + (size_t)1 * HID);

    for (int t = 0; t < S_LEN; ++t) {
        // prefetch gates for t+2
        float4 gq2 = make_float4(0.f, 0.f, 0.f, 0.f);
        if (t + 2 < S_LEN) gq2 = __ldcg(gbase + (size_t)(t + 2) * HID);

        const int par = (t - 1) & 1;

        if (t > 0) {
            // ---- phase A: wait for half0 producers (blocks 0..63) --------
            const unsigned* cp = &g_ctr[warp][0][layer][t - 1];
            unsigned v = ldacq(cp);
            int spins = 0;
            while (v < 64u) {
                if (spins >= 8) __nanosleep(40);   // validated fallback
                ++spins;
                v = ldacq(cp);                     // RT-paced dependent reload
            }
            // stage h[0:512]: thread tid covers h[2*tid], h[2*tid+1]
            float2 hv = __ldcg((const float2*)&g_hv[par][2 * tid]);
            *(float2*)&sm_h[par][2 * tid] = hv;
        }
        __syncthreads();

        unsigned long long a0 = 0, a1 = 0, a2 = 0, a3 = 0;
        if (t > 0) {
            // ---- GEMV half0 (k = 0..511) while half1 lands ----
            const float* hs = sm_h[par];
#pragma unroll
            for (int it = 0; it < 4; ++it) {
                union { float4 f4; unsigned long long u[2]; } hv;
                hv.f4 = *(const float4*)(hs + it * 128 + lane * 4);
                ffma2(a0, hv.u[0], w[0][it][0]); ffma2(a0, hv.u[1], w[0][it][1]);
                ffma2(a1, hv.u[0], w[1][it][0]); ffma2(a1, hv.u[1], w[1][it][1]);
                ffma2(a2, hv.u[0], w[2][it][0]); ffma2(a2, hv.u[1], w[2][it][1]);
                ffma2(a3, hv.u[0], w[3][it][0]); ffma2(a3, hv.u[1], w[3][it][1]);
            }
            // ---- phase B: wait for half1 producers (blocks 64..127) ------
            const unsigned* cp = &g_ctr[warp][1][layer][t - 1];
            unsigned v = ldacq(cp);
            int spins = 0;
            while (v < 64u) {
                if (spins >= 8) __nanosleep(40);
                ++spins;
                v = ldacq(cp);
            }
            float2 hv = __ldcg((const float2*)&g_hv[par][512 + 2 * tid]);
            *(float2*)&sm_h[par][512 + 2 * tid] = hv;
        }
        __syncthreads();

        if (t > 0) {
            // ---- GEMV half1 (k = 512..1023) ----
            const float* hs = sm_h[par];
#pragma unroll
            for (int it = 4; it < 8; ++it) {
                union { float4 f4; unsigned long long u[2]; } hv;
                hv.f4 = *(const float4*)(hs + it * 128 + lane * 4);
                ffma2(a0, hv.u[0], w[0][it][0]); ffma2(a0, hv.u[1], w[0][it][1]);
                ffma2(a1, hv.u[0], w[1][it][0]); ffma2(a1, hv.u[1], w[1][it][1]);
                ffma2(a2, hv.u[0], w[2][it][0]); ffma2(a2, hv.u[1], w[2][it][1]);
                ffma2(a3, hv.u[0], w[3][it][0]); ffma2(a3, hv.u[1], w[3][it][1]);
            }
        }

        float2 p;
        p = unpack2(a0); float si = p.x + p.y;
        p = unpack2(a1); float sf = p.x + p.y;
        p = unpack2(a2); float sg = p.x + p.y;
        p = unpack2(a3); float so = p.x + p.y;
#pragma unroll
        for (int off = 16; off; off >>= 1) {
            si += __shfl_xor_sync(0xffffffffu, si, off);
            sf += __shfl_xor_sync(0xffffffffu, sf, off);
            sg += __shfl_xor_sync(0xffffffffu, sg, off);
            so += __shfl_xor_sync(0xffffffffu, so, off);
        }
        // butterfly left full sums in every lane; all lanes compute the
        // epilogue redundantly (no broadcast shuffles on the chain)
        float i_  = sigmoidf_(si + gq.x);
        float f_  = sigmoidf_(sf + gq.y);
        float gg_ = tanhf_  (sg + gq.z);
        float o_  = sigmoidf_(so + gq.w);
        c = f_ * c + i_ * gg_;
        float hn = o_ * tanhf_(c);
        if (lane == 0) {
            __stcg(&g_hv[t & 1][j], hn);        // bare value publish
            y_out[(size_t)t * HID + j] = hn;
        }
        // ---- release this block's half epoch: bar orders ALL warps'
        //      publishes before the release-adds (R12 pattern) -------------
        __syncthreads();
        if (tid < 8) redrel(&g_ctr[tid][half][layer][t]);

        gq = gq1; gq1 = gq2;
    }
}

// ---------------- final FC: out = h_last . fc_w + fc_b ---------------------
__global__ void fc_kernel(const float* __restrict__ w,
                          const float* __restrict__ b,
                          float* __restrict__ out)
{
    const float* h = g_yB + (size_t)(S_LEN - 1) * HID;
    const int tid = threadIdx.x;
    float s = 0.0f;
    for (int k = tid; k < HID; k += 256) s += h[k] * w[k];
#pragma unroll
    for (int off = 16; off; off >>= 1) s += __shfl_xor_sync(0xffffffffu, s, off);
    __shared__ float red[8];
    if ((tid & 31) == 0) red[tid >> 5] = s;
    __syncthreads();
    if (tid == 0) {
        float tot = 0.0f;
#pragma unroll
        for (int i = 0; i < 8; ++i) tot += red[i];
        out[0] = tot + b[0];
    }
}

// ---------------- launch ----------------------------------------------------
extern "C" void kernel_launch(void* const* d_in, const int* in_sizes, int n_in,
                              void* d_out, int out_size)
{
    (void)in_sizes; (void)n_in; (void)out_size;
    const float* seq   = (const float*)d_in[0];
    const float* w_ih0 = (const float*)d_in[1];
    const float* w_hh0 = (const float*)d_in[2];
    const float* b0    = (const float*)d_in[3];
    const float* w_ih1 = (const float*)d_in[4];
    const float* w_hh1 = (const float*)d_in[5];
    const float* b1    = (const float*)d_in[6];
    const float* w_ih2 = (const float*)d_in[7];
    const float* w_hh2 = (const float*)d_in[8];
    const float* b2    = (const float*)d_in[9];
    const float* w_ih3 = (const float*)d_in[10];
    const float* w_hh3 = (const float*)d_in[11];
    const float* b3    = (const float*)d_in[12];
    const float* fc_w  = (const float*)d_in[13];
    const float* fc_b  = (const float*)d_in[14];
    float* out = (float*)d_out;

    dim3 ggrid(G4 / 128, S_LEN / 128);

    // fresh epoch counters every replay
    zero_ctr_kernel<<<2048, 256>>>();

    // layer 0
    gemm_xwt<<<ggrid, 256>>>(seq, 0, w_ih0, b0, 256);
    lstm_scan<<<128, 256>>>(w_hh0, 1, 0);   // -> g_yA
    // layer 1
    gemm_xwt<<<ggrid, 256>>>(nullptr, 1, w_ih1, b1, HID);
    lstm_scan<<<128, 256>>>(w_hh1, 2, 1);   // -> g_yB
    // layer 2
    gemm_xwt<<<ggrid, 256>>>(nullptr, 2, w_ih2, b2, HID);
    lstm_scan<<<128, 256>>>(w_hh2, 1, 2);   // -> g_yA
    // layer 3
    gemm_xwt<<<ggrid, 256>>>(nullptr, 1, w_ih3, b3, HID);
    lstm_scan<<<128, 256>>>(w_hh3, 2, 3);   // -> g_yB
    // head
    fc_kernel<<<1, 256>>>(fc_w, fc_b, out);
}

// round 17
// speedup vs baseline: 3.3677x; 1.4194x over previous
#include <cuda_runtime.h>
#include <cstdint>
#include <cstddef>

#define S_LEN 8192
#define HID   1024
#define G4    4096   // 4*HID
#define HGRID 20     // helper gemm blocks: <= 148-128 SMs, 1 block/SM by regs

// ---------------- scratch (device globals: allocation-free) ----------------
// gates DOUBLE-buffered: gemm(l+1) runs concurrently with scan(l); layer l
// uses buffer l&1.
__device__ float g_gates[2][(size_t)S_LEN * G4];   // 2 x 128 MB
__device__ float g_yA[(size_t)S_LEN * HID];        // 32 MB: layer outputs ping
__device__ float g_yB[(size_t)S_LEN * HID];        // 32 MB: layer outputs pong
// hidden state values, double-buffered by step parity (bare values; ordering
// carried entirely by the epoch counters below)
__device__ __align__(16) float g_hv[2][HID];
// R12-validated epoch counters: [replica 0..7][layer][t]. Producer block adds
// 1 to every replica after publishing its h slice (release); consumer warp w
// polls replica w (acquire) until it reaches 128. Replica planes 128KB apart.
// ALSO consumed by the helper gemm (row-readiness polling).
__device__ unsigned g_ctr[8][4][S_LEN];            // 1 MB

// ---------------- packed f32x2 helpers (sm_103a FFMA2) ----------------
__device__ __forceinline__ void ffma2(unsigned long long& d,
                                      unsigned long long a,
                                      unsigned long long b) {
    asm("fma.rn.f32x2 %0, %1, %2, %0;" : "+l"(d) : "l"(a), "l"(b));
}
__device__ __forceinline__ unsigned long long pack2(float x, float y) {
    unsigned long long r;
    asm("mov.b64 %0, {%1, %2};" : "=l"(r)
        : "r"(__float_as_uint(x)), "r"(__float_as_uint(y)));
    return r;
}
__device__ __forceinline__ float2 unpack2(unsigned long long v) {
    unsigned int lo, hi;
    asm("mov.b64 {%0, %1}, %2;" : "=r"(lo), "=r"(hi) : "l"(v));
    float2 r; r.x = __uint_as_float(lo); r.y = __uint_as_float(hi);
    return r;
}

__device__ __forceinline__ float sigmoidf_(float x) {
    return __fdividef(1.0f, 1.0f + __expf(-x));
}
// fast, overflow-safe tanh: tanh(x) = sign(x) * (1-e)/(1+e), e = exp(-2|x|)
__device__ __forceinline__ float tanhf_(float x) {
    float e = __expf(-2.0f * fabsf(x));
    float r = __fdividef(1.0f - e, 1.0f + e);
    return copysignf(r, x);
}

// release/acquire epoch ops (the cooperative-groups grid-sync pattern)
__device__ __forceinline__ unsigned ldacq(const unsigned* p) {
    unsigned v;
    asm volatile("ld.acquire.gpu.global.u32 %0, [%1];" : "=r"(v) : "l"(p));
    return v;
}
__device__ __forceinline__ void redrel(unsigned* p) {
    asm volatile("red.release.gpu.global.add.u32 [%0], 1;" :: "l"(p) : "memory");
}

// ---------------- zero the epoch counters (fresh every replay) -------------
__global__ void zero_ctr_kernel() {
    int i = blockIdx.x * blockDim.x + threadIdx.x;
    if (i < 8 * 4 * S_LEN) ((unsigned*)g_ctr)[i] = 0u;
}

// ---------------- GEMM (layer 0 only): full-grid, no dependency ------------
// gates[0][S][HID][4] = X[S,256] @ W[4H,256]^T + b. BM=BN=128, BK=16.
__global__ __launch_bounds__(256)
void gemm_xwt(const float* __restrict__ X,
              const float* __restrict__ W, const float* __restrict__ bias,
              int K)
{
    float* gates = g_gates[0];

    __shared__ float a_s[16][128];
    __shared__ float b_s[16][128];

    const int tid = threadIdx.x;
    const int bm = blockIdx.y * 128;
    const int bn = blockIdx.x * 128;
    const int tx = tid & 15;
    const int ty = tid >> 4;

    unsigned long long acc[8][4];
#pragma unroll
    for (int i = 0; i < 8; ++i)
#pragma unroll
        for (int jp = 0; jp < 4; ++jp) acc[i][jp] = 0ull;

    for (int k0 = 0; k0 < K; k0 += 16) {
#pragma unroll
        for (int r = 0; r < 2; ++r) {
            int q   = tid + r * 256;
            int row = q >> 2;
            int kq  = (q & 3) << 2;
            float4 va = *(const float4*)(X + (size_t)(bm + row) * K + k0 + kq);
            a_s[kq + 0][row] = va.x; a_s[kq + 1][row] = va.y;
            a_s[kq + 2][row] = va.z; a_s[kq + 3][row] = va.w;
            float4 vb = *(const float4*)(W + (size_t)(bn + row) * K + k0 + kq);
            b_s[kq + 0][row] = vb.x; b_s[kq + 1][row] = vb.y;
            b_s[kq + 2][row] = vb.z; b_s[kq + 3][row] = vb.w;
        }
        __syncthreads();
#pragma unroll
        for (int kk = 0; kk < 16; ++kk) {
            float4 a0 = *(const float4*)&a_s[kk][ty * 8];
            float4 a1 = *(const float4*)&a_s[kk][ty * 8 + 4];
            float4 b0 = *(const float4*)&b_s[kk][tx * 8];
            float4 b1 = *(const float4*)&b_s[kk][tx * 8 + 4];
            unsigned long long bp0 = pack2(b0.x, b0.y);
            unsigned long long bp1 = pack2(b0.z, b0.w);
            unsigned long long bp2 = pack2(b1.x, b1.y);
            unsigned long long bp3 = pack2(b1.z, b1.w);
            float av[8] = {a0.x, a0.y, a0.z, a0.w, a1.x, a1.y, a1.z, a1.w};
#pragma unroll
            for (int i = 0; i < 8; ++i) {
                unsigned long long ap = pack2(av[i], av[i]);
                ffma2(acc[i][0], ap, bp0);
                ffma2(acc[i][1], ap, bp1);
                ffma2(acc[i][2], ap, bp2);
                ffma2(acc[i][3], ap, bp3);
            }
        }
        __syncthreads();
    }

    const int gate = bn >> 10;
#pragma unroll
    for (int i = 0; i < 8; ++i) {
        size_t row = (size_t)(bm + ty * 8 + i);
#pragma unroll
        for (int jp = 0; jp < 4; ++jp) {
            int col = bn + tx * 8 + jp * 2;
            int jj  = col - (gate << 10);
            float2 v = unpack2(acc[i][jp]);
            gates[row * G4 + (size_t)jj * 4 + gate]       = v.x + bias[col];
            gates[row * G4 + (size_t)(jj + 1) * 4 + gate] = v.y + bias[col + 1];
        }
    }
}

// ---------------- persistent helper GEMM (layers 1-3, overlapped) ----------
// Runs on the <=20 SMs the scan leaves free (HGRID blocks x 512 threads x
// ~128 regs = 1 block/SM; scan's 128 blocks own the other 128 SMs — packing
// is exact, so no dispatch order can deadlock). Each block loops over
// 256x128 tiles of gates[gbuf] = Y[dep_layer] @ W^T + b, polling the scan's
// epoch counter for row bm+255 before each tile (acquire; the scan's
// release-add orders its y stores).
__global__ __launch_bounds__(512, 1)
void gemm_helper(int xsel, const float* __restrict__ W,
                 const float* __restrict__ bias, int dep_layer, int gbuf)
{
    const float* X = (xsel == 1) ? g_yA : g_yB;   // K = HID
    float* gates = g_gates[gbuf];

    __shared__ float a_s[16][256];
    __shared__ float b_s[16][128];

    const int tid = threadIdx.x;
    const int tx = tid & 15;    // 0..15 -> N (8 cols each)
    const int ty = tid >> 4;    // 0..31 -> M (8 rows each, 256 rows)

    const int NT = (S_LEN / 256) * (G4 / 128);    // 32*32 = 1024 tiles

    for (int tile = blockIdx.x; tile < NT; tile += HGRID) {
        const int bm = (tile >> 5) * 256;         // bm-major: trails the scan
        const int bn = (tile & 31) * 128;

        // ---- row-readiness: rows bm..bm+255 need scan step bm+255 --------
        if (tid == 0) {
            const unsigned* cp = &g_ctr[blockIdx.x & 7][dep_layer][bm + 255];
            unsigned v = ldacq(cp);
            int spins = 0;
            while (v < 128u) {
                if (spins >= 4) __nanosleep(200);
                ++spins;
                v = ldacq(cp);
            }
        }
        __syncthreads();

        unsigned long long acc[8][4];
#pragma unroll
        for (int i = 0; i < 8; ++i)
#pragma unroll
            for (int jp = 0; jp < 4; ++jp) acc[i][jp] = 0ull;

        for (int k0 = 0; k0 < HID; k0 += 16) {
            // a_s: 256 rows x 16 k = 1024 float4, 2 per thread
#pragma unroll
            for (int r = 0; r < 2; ++r) {
                int q   = tid + r * 512;
                int row = q >> 2;              // 0..255
                int kq  = (q & 3) << 2;
                float4 va = *(const float4*)(X + (size_t)(bm + row) * HID + k0 + kq);
                a_s[kq + 0][row] = va.x; a_s[kq + 1][row] = va.y;
                a_s[kq + 2][row] = va.z; a_s[kq + 3][row] = va.w;
            }
            // b_s: 128 rows x 16 k = 512 float4, 1 per thread
            {
                int row = tid >> 2;            // 0..127
                int kq  = (tid & 3) << 2;
                float4 vb = *(const float4*)(W + (size_t)(bn + row) * HID + k0 + kq);
                b_s[kq + 0][row] = vb.x; b_s[kq + 1][row] = vb.y;
                b_s[kq + 2][row] = vb.z; b_s[kq + 3][row] = vb.w;
            }
            __syncthreads();
#pragma unroll
            for (int kk = 0; kk < 16; ++kk) {
                float4 a0 = *(const float4*)&a_s[kk][ty * 8];
                float4 a1 = *(const float4*)&a_s[kk][ty * 8 + 4];
                float4 b0 = *(const float4*)&b_s[kk][tx * 8];
                float4 b1 = *(const float4*)&b_s[kk][tx * 8 + 4];
                unsigned long long bp0 = pack2(b0.x, b0.y);
                unsigned long long bp1 = pack2(b0.z, b0.w);
                unsigned long long bp2 = pack2(b1.x, b1.y);
                unsigned long long bp3 = pack2(b1.z, b1.w);
                float av[8] = {a0.x, a0.y, a0.z, a0.w, a1.x, a1.y, a1.z, a1.w};
#pragma unroll
                for (int i = 0; i < 8; ++i) {
                    unsigned long long ap = pack2(av[i], av[i]);
                    ffma2(acc[i][0], ap, bp0);
                    ffma2(acc[i][1], ap, bp1);
                    ffma2(acc[i][2], ap, bp2);
                    ffma2(acc[i][3], ap, bp3);
                }
            }
            __syncthreads();
        }

        const int gate = bn >> 10;
#pragma unroll
        for (int i = 0; i < 8; ++i) {
            size_t row = (size_t)(bm + ty * 8 + i);
#pragma unroll
            for (int jp = 0; jp < 4; ++jp) {
                int col = bn + tx * 8 + jp * 2;
                int jj  = col - (gate << 10);
                float2 v = unpack2(acc[i][jp]);
                gates[row * G4 + (size_t)jj * 4 + gate]       = v.x + bias[col];
                gates[row * G4 + (size_t)(jj + 1) * 4 + gate] = v.y + bias[col + 1];
            }
        }
        __syncthreads();   // a_s/b_s reuse safety across tiles
    }
}

// ---------------- persistent recurrent scan (one launch per layer) ---------
// EXACT R12 configuration (the validated 14.4 ms/layer optimum — frozen).
__global__ __launch_bounds__(256, 1)
void lstm_scan(const float* __restrict__ w_hh, int ysel, int layer)
{
    float* y_out = (ysel == 1) ? g_yA : g_yB;
    const float* gates = g_gates[layer & 1];

    __shared__ __align__(16) float sm_h[2][HID];   // double-buffered staged h

    const int tid  = threadIdx.x;
    const int lane = tid & 31;
    const int warp = tid >> 5;
    const int j    = blockIdx.x * 8 + warp;    // 0..1023

    unsigned long long w[4][8][2];
#pragma unroll
    for (int g = 0; g < 4; ++g)
#pragma unroll
        for (int it = 0; it < 8; ++it) {
            union { float4 f4; unsigned long long u[2]; } t;
            t.f4 = *(const float4*)(w_hh + (size_t)(g * HID + j) * HID
                                    + it * 128 + lane * 4);
            w[g][it][0] = t.u[0];
            w[g][it][1] = t.u[1];
        }

    float c = 0.0f;

    const float4* gbase = (const float4*)gates + j;
    float4 gq  = __ldcg(gbase + (size_t)0 * HID);
    float4 gq1 = __ldcg(gbase + (size_t)1 * HID);

    for (int t = 0; t < S_LEN; ++t) {
        float4 gq2 = make_float4(0.f, 0.f, 0.f, 0.f);
        if (t + 2 < S_LEN) gq2 = __ldcg(gbase + (size_t)(t + 2) * HID);

        const int par = (t - 1) & 1;

        if (t > 0) {
            const unsigned* cp = &g_ctr[warp][layer][t - 1];
            unsigned v = ldacq(cp);
            int spins = 0;
            while (v < 128u) {
                if (spins >= 8) __nanosleep(40);
                ++spins;
                v = ldacq(cp);
            }
            float4 hv = __ldcg((const float4*)&g_hv[par][4 * tid]);
            *(float4*)&sm_h[par][4 * tid] = hv;
        }
        __syncthreads();

        unsigned long long a0 = 0, a1 = 0, a2 = 0, a3 = 0;
        if (t > 0) {
            const float* hs = sm_h[par];
#pragma unroll
            for (int it = 0; it < 8; ++it) {
                union { float4 f4; unsigned long long u[2]; } hv;
                hv.f4 = *(const float4*)(hs + it * 128 + lane * 4);
                ffma2(a0, hv.u[0], w[0][it][0]); ffma2(a0, hv.u[1], w[0][it][1]);
                ffma2(a1, hv.u[0], w[1][it][0]); ffma2(a1, hv.u[1], w[1][it][1]);
                ffma2(a2, hv.u[0], w[2][it][0]); ffma2(a2, hv.u[1], w[2][it][1]);
                ffma2(a3, hv.u[0], w[3][it][0]); ffma2(a3, hv.u[1], w[3][it][1]);
            }
        }

        float2 p;
        p = unpack2(a0); float si = p.x + p.y;
        p = unpack2(a1); float sf = p.x + p.y;
        p = unpack2(a2); float sg = p.x + p.y;
        p = unpack2(a3); float so = p.x + p.y;
#pragma unroll
        for (int off = 16; off; off >>= 1) {
            si += __shfl_xor_sync(0xffffffffu, si, off);
            sf += __shfl_xor_sync(0xffffffffu, sf, off);
            sg += __shfl_xor_sync(0xffffffffu, sg, off);
            so += __shfl_xor_sync(0xffffffffu, so, off);
        }
        float i_  = sigmoidf_(si + gq.x);
        float f_  = sigmoidf_(sf + gq.y);
        float gg_ = tanhf_  (sg + gq.z);
        float o_  = sigmoidf_(so + gq.w);
        c = f_ * c + i_ * gg_;
        float hn = o_ * tanhf_(c);
        if (lane == 0) {
            __stcg(&g_hv[t & 1][j], hn);
            y_out[(size_t)t * HID + j] = hn;    // released by redrel below
        }
        __syncthreads();
        if (tid < 8) redrel(&g_ctr[tid][layer][t]);

        gq = gq1; gq1 = gq2;
    }
}

// ---------------- final FC: out = h_last . fc_w + fc_b ---------------------
__global__ void fc_kernel(const float* __restrict__ w,
                          const float* __restrict__ b,
                          float* __restrict__ out)
{
    const float* h = g_yB + (size_t)(S_LEN - 1) * HID;
    const int tid = threadIdx.x;
    float s = 0.0f;
    for (int k = tid; k < HID; k += 256) s += h[k] * w[k];
#pragma unroll
    for (int off = 16; off; off >>= 1) s += __shfl_xor_sync(0xffffffffu, s, off);
    __shared__ float red[8];
    if ((tid & 31) == 0) red[tid >> 5] = s;
    __syncthreads();
    if (tid == 0) {
        float tot = 0.0f;
#pragma unroll
        for (int i = 0; i < 8; ++i) tot += red[i];
        out[0] = tot + b[0];
    }
}

// ---------------- launch ----------------------------------------------------
// Main stream: zero_ctr -> gemm0 -> scan0..scan3 -> fc.
// s2: helper gemm(l+1) (HGRID blocks, deadlock-free packing) overlaps scan(l).
extern "C" void kernel_launch(void* const* d_in, const int* in_sizes, int n_in,
                              void* d_out, int out_size)
{
    (void)in_sizes; (void)n_in; (void)out_size;
    const float* seq   = (const float*)d_in[0];
    const float* w_ih0 = (const float*)d_in[1];
    const float* w_hh0 = (const float*)d_in[2];
    const float* b0    = (const float*)d_in[3];
    const float* w_ih1 = (const float*)d_in[4];
    const float* w_hh1 = (const float*)d_in[5];
    const float* b1    = (const float*)d_in[6];
    const float* w_ih2 = (const float*)d_in[7];
    const float* w_hh2 = (const float*)d_in[8];
    const float* b2    = (const float*)d_in[9];
    const float* w_ih3 = (const float*)d_in[10];
    const float* w_hh3 = (const float*)d_in[11];
    const float* b3    = (const float*)d_in[12];
    const float* fc_w  = (const float*)d_in[13];
    const float* fc_b  = (const float*)d_in[14];
    float* out = (float*)d_out;

    static cudaStream_t s2 = nullptr;
    static cudaEvent_t evF1, evF2, evF3, evJ1, evJ2, evJ3;
    if (!s2) {
        cudaStreamCreateWithFlags(&s2, cudaStreamNonBlocking);
        cudaEventCreateWithFlags(&evF1, cudaEventDisableTiming);
        cudaEventCreateWithFlags(&evF2, cudaEventDisableTiming);
        cudaEventCreateWithFlags(&evF3, cudaEventDisableTiming);
        cudaEventCreateWithFlags(&evJ1, cudaEventDisableTiming);
        cudaEventCreateWithFlags(&evJ2, cudaEventDisableTiming);
        cudaEventCreateWithFlags(&evJ3, cudaEventDisableTiming);
    }

    dim3 ggrid(G4 / 128, S_LEN / 128);

    zero_ctr_kernel<<<1024, 256>>>();
    gemm_xwt<<<ggrid, 256>>>(seq, w_ih0, b0, 256);      // gates buf 0

    cudaEventRecord(evF1, 0);                           // after gemm0
    lstm_scan<<<128, 256>>>(w_hh0, 1, 0);               // scan0 -> g_yA
    cudaEventRecord(evF2, 0);                           // after scan0

    // helper1 overlaps scan0 (reads g_yA progressively, writes gates buf 1)
    cudaStreamWaitEvent(s2, evF1, 0);
    gemm_helper<<<HGRID, 512, 0, s2>>>(1, w_ih1, b1, 0, 1);
    cudaEventRecord(evJ1, s2);

    // helper2 overlaps scan1 (writes gates buf 0, free once scan0 done)
    cudaStreamWaitEvent(s2, evF2, 0);
    gemm_helper<<<HGRID, 512, 0, s2>>>(2, w_ih2, b2, 1, 0);
    cudaEventRecord(evJ2, s2);

    cudaStreamWaitEvent(0, evJ1, 0);                    // gemm1 before scan1
    lstm_scan<<<128, 256>>>(w_hh1, 2, 1);               // scan1 -> g_yB
    cudaEventRecord(evF3, 0);                           // after scan1

    // helper3 overlaps scan2 (writes gates buf 1, free once scan1 done)
    cudaStreamWaitEvent(s2, evF3, 0);
    gemm_helper<<<HGRID, 512, 0, s2>>>(1, w_ih3, b3, 2, 1);
    cudaEventRecord(evJ3, s2);

    cudaStreamWaitEvent(0, evJ2, 0);                    // gemm2 before scan2
    lstm_scan<<<128, 256>>>(w_hh2, 1, 2);               // scan2 -> g_yA

    cudaStreamWaitEvent(0, evJ3, 0);                    // gemm3 before scan3
    lstm_scan<<<128, 256>>>(w_hh3, 2, 3);               // scan3 -> g_yB

    fc_kernel<<<1, 256>>>(fc_w, fc_b, out);
}